// round 7
// baseline (speedup 1.0000x reference)
#include <cuda_runtime.h>
#include <cuda_fp16.h>
#include <cstdint>
#include <cstddef>

// ---------------- problem dims ----------------
#define MM 16384    // B*S
#define NN 4096     // DOUT
#define KK 4096     // DIN

#define BM 128
#define BN 128
#define BK 64
#define NKT (KK / BK)      // 64
#define GRID_M (MM / BM)   // 128
#define GRID_N (NN / BN)   // 32
#define THREADS 256
#define STAGES 3

#define STAGE_BYTES (BM * BK * 2 + BN * BK * 2)   // 16KB A + 16KB B = 32KB
#define SMEM_DYN (STAGES * STAGE_BYTES + 256)     // ~96.25KB -> 2 CTAs/SM

// ---------------- device scratch ----------------
__device__ __half g_A[(size_t)MM * KK];   // x in fp16 (128 MB)
__device__ __half g_W[(size_t)NN * KK];   // quantized weights: exact small integers in fp16
__device__ float  g_qb[NN];               // quantized bias * (1/255)

// ---------------- helpers ----------------
__device__ __forceinline__ uint32_t smem_u32(const void* p) {
    uint32_t a;
    asm("{ .reg .u64 t; cvta.to.shared.u64 t, %1; cvt.u32.u64 %0, t; }" : "=r"(a) : "l"(p));
    return a;
}
__device__ __forceinline__ void cp_async_cg(uint32_t s, const void* g) {
    asm volatile("cp.async.cg.shared.global [%0], [%1], 16;" :: "r"(s), "l"(g));
}
__device__ __forceinline__ void cp_commit() { asm volatile("cp.async.commit_group;" ::: "memory"); }

__device__ __forceinline__ void ldmatrix_x4(uint32_t& r0, uint32_t& r1, uint32_t& r2, uint32_t& r3,
                                            uint32_t addr) {
    asm volatile("ldmatrix.sync.aligned.m8n8.x4.shared.b16 {%0,%1,%2,%3}, [%4];"
                 : "=r"(r0), "=r"(r1), "=r"(r2), "=r"(r3) : "r"(addr));
}
__device__ __forceinline__ void mma16816(float& c0, float& c1, float& c2, float& c3,
                                         uint32_t a0, uint32_t a1, uint32_t a2, uint32_t a3,
                                         uint32_t b0, uint32_t b1) {
    asm volatile("mma.sync.aligned.m16n8k16.row.col.f32.f16.f16.f32 "
                 "{%0,%1,%2,%3}, {%4,%5,%6,%7}, {%8,%9}, {%0,%1,%2,%3};"
                 : "+f"(c0), "+f"(c1), "+f"(c2), "+f"(c3)
                 : "r"(a0), "r"(a1), "r"(a2), "r"(a3), "r"(b0), "r"(b1));
}

// ---------------- prepass kernels ----------------
__device__ __forceinline__ float qstep(float t) {
    t = fminf(fmaxf(t, -1.0f), 1.0f);
    return copysignf(rintf(fabsf(t) * 255.0f), t);   // exact integer in [-255, 255]
}

__global__ void cvt_x_kernel(const float4* __restrict__ x) {
    size_t i = (size_t)blockIdx.x * blockDim.x + threadIdx.x;
    float4 v = x[i];
    __half2* a2 = reinterpret_cast<__half2*>(g_A);
    a2[2 * i]     = __floats2half2_rn(v.x, v.y);
    a2[2 * i + 1] = __floats2half2_rn(v.z, v.w);
}

__global__ void quant_w_kernel(const float4* __restrict__ w) {
    size_t i = (size_t)blockIdx.x * blockDim.x + threadIdx.x;
    float4 v = w[i];
    __half2* w2 = reinterpret_cast<__half2*>(g_W);
    w2[2 * i]     = __floats2half2_rn(qstep(v.x), qstep(v.y));  // exact
    w2[2 * i + 1] = __floats2half2_rn(qstep(v.z), qstep(v.w));
}

__global__ void quant_b_kernel(const float* __restrict__ b) {
    int i = blockIdx.x * blockDim.x + threadIdx.x;
    g_qb[i] = qstep(b[i]) * (1.0f / 255.0f);
}

// ---------------- GEMM: cp.async triple-buffer + ldmatrix + mma.sync ----------------
// SMEM tile layout (per stage): rows of 64 halves = 8 chunks of 16B.
// chunk swizzle: physical chunk = c ^ (row & 7)  -> conflict-free cp.async stores
// and ldmatrix reads.
__global__ void __launch_bounds__(THREADS, 2)
gemm_kernel(float* __restrict__ out) {
    extern __shared__ char dynsmem[];
    uint32_t sb = (smem_u32(dynsmem) + 255u) & ~255u;

    const int tid  = threadIdx.x;
    const int lane = tid & 31;
    const int wid  = tid >> 5;
    const int wm   = wid & 3;    // 4 warps along M: 32 rows each
    const int wn   = wid >> 2;   // 2 warps along N: 64 cols each
    const int mtile = blockIdx.x;
    const int ntile = blockIdx.y;

    const __half* Ab = g_A + (size_t)mtile * BM * KK;
    const __half* Wb = g_W + (size_t)ntile * BN * KK;

    // per-stage loader: A tile 128x64, B tile 128x64; 1024 chunks each, 4+4 per thread
    auto load_tile = [&](int kt, int s) {
        uint32_t abase = sb + s * STAGE_BYTES;
        uint32_t bbase = abase + BM * BK * 2;
        const __half* Ak = Ab + (size_t)kt * BK;
        const __half* Wk = Wb + (size_t)kt * BK;
        #pragma unroll
        for (int j = 0; j < 4; j++) {
            int id = j * THREADS + tid;
            int row = id >> 3, c = id & 7;
            uint32_t dst = (uint32_t)(row * 8 + (c ^ (row & 7))) * 16;
            cp_async_cg(abase + dst, Ak + (size_t)row * KK + c * 8);
        }
        #pragma unroll
        for (int j = 0; j < 4; j++) {
            int id = j * THREADS + tid;
            int row = id >> 3, c = id & 7;
            uint32_t dst = (uint32_t)(row * 8 + (c ^ (row & 7))) * 16;
            cp_async_cg(bbase + dst, Wk + (size_t)row * KK + c * 8);
        }
        cp_commit();
    };

    float acc[2][8][4];
    #pragma unroll
    for (int i = 0; i < 2; i++)
        #pragma unroll
        for (int j = 0; j < 8; j++)
            #pragma unroll
            for (int k = 0; k < 4; k++) acc[i][j][k] = 0.0f;

    const int lrow = lane & 15;   // ldmatrix row within 16
    const int lsel = lane >> 4;   // ldmatrix chunk select (0/1)

    load_tile(0, 0);
    load_tile(1, 1);
    load_tile(2, 2);

    int s = 0;
    for (int kt = 0; kt < NKT; kt++) {
        if (kt + 3 < NKT)      asm volatile("cp.async.wait_group 2;" ::: "memory");
        else if (kt + 2 < NKT) asm volatile("cp.async.wait_group 1;" ::: "memory");
        else                   asm volatile("cp.async.wait_group 0;" ::: "memory");
        __syncthreads();

        uint32_t abase = sb + s * STAGE_BYTES;
        uint32_t bbase = abase + BM * BK * 2;

        #pragma unroll
        for (int ks = 0; ks < 4; ks++) {          // BK=64 -> 4 k16 steps
            // A fragments: 2 m16 tiles
            uint32_t a[2][4];
            #pragma unroll
            for (int mt = 0; mt < 2; mt++) {
                int r = wm * 32 + mt * 16 + lrow;
                int c = ks * 2 + lsel;
                uint32_t addr = abase + (uint32_t)(r * 8 + (c ^ (r & 7))) * 16;
                ldmatrix_x4(a[mt][0], a[mt][1], a[mt][2], a[mt][3], addr);
            }
            // B fragments: 4 n16 tiles (each = two n8 frags)
            uint32_t b[4][4];
            #pragma unroll
            for (int nt = 0; nt < 4; nt++) {
                int r = wn * 64 + nt * 16 + lrow;
                int c = ks * 2 + lsel;
                uint32_t addr = bbase + (uint32_t)(r * 8 + (c ^ (r & 7))) * 16;
                ldmatrix_x4(b[nt][0], b[nt][1], b[nt][2], b[nt][3], addr);
            }
            #pragma unroll
            for (int mt = 0; mt < 2; mt++)
                #pragma unroll
                for (int nt = 0; nt < 4; nt++) {
                    // n8 frag 0: regs {0,2}; n8 frag 1: regs {1,3}
                    mma16816(acc[mt][nt*2][0], acc[mt][nt*2][1], acc[mt][nt*2][2], acc[mt][nt*2][3],
                             a[mt][0], a[mt][1], a[mt][2], a[mt][3], b[nt][0], b[nt][2]);
                    mma16816(acc[mt][nt*2+1][0], acc[mt][nt*2+1][1], acc[mt][nt*2+1][2], acc[mt][nt*2+1][3],
                             a[mt][0], a[mt][1], a[mt][2], a[mt][3], b[nt][1], b[nt][3]);
                }
        }
        __syncthreads();
        if (kt + 3 < NKT) load_tile(kt + 3, s);
        s = (s == STAGES - 1) ? 0 : s + 1;
    }

    // ---------------- epilogue: out = acc * (1/255) + qb ----------------
    const int tm = lane >> 2;          // 0..7
    const int tn = (lane & 3) * 2;     // 0,2,4,6
    const float inv = 1.0f / 255.0f;   // weights stored as integer codes k = qw*255
    const float* qbb = g_qb + ntile * BN + wn * 64;

    float2 bias[8];
    #pragma unroll
    for (int nn = 0; nn < 8; nn++) {
        int col = (nn >> 1) * 16 + (nn & 1) * 8 + tn;
        bias[nn] = *(const float2*)(qbb + col);
    }

    #pragma unroll
    for (int mt = 0; mt < 2; mt++) {
        #pragma unroll
        for (int h = 0; h < 2; h++) {           // c0c1 (row+0) / c2c3 (row+8)
            int row = mtile * BM + wm * 32 + mt * 16 + tm + h * 8;
            float* orow = out + (size_t)row * NN + ntile * BN + wn * 64;
            #pragma unroll
            for (int nn = 0; nn < 8; nn++) {
                int col = (nn >> 1) * 16 + (nn & 1) * 8 + tn;
                float2 v;
                v.x = fmaf(acc[mt][nn][h * 2 + 0], inv, bias[nn].x);
                v.y = fmaf(acc[mt][nn][h * 2 + 1], inv, bias[nn].y);
                *(float2*)(orow + col) = v;
            }
        }
    }
}

// ---------------- launch ----------------
extern "C" void kernel_launch(void* const* d_in, const int* in_sizes, int n_in,
                              void* d_out, int out_size) {
    const float* x = (const float*)d_in[0];
    const float* w = (const float*)d_in[1];
    const float* b = (const float*)d_in[2];
    float* out = (float*)d_out;

    cvt_x_kernel<<<(MM * (size_t)KK / 4) / 256, 256>>>((const float4*)x);
    quant_w_kernel<<<(NN * (size_t)KK / 4) / 256, 256>>>((const float4*)w);
    quant_b_kernel<<<NN / 256, 256>>>(b);

    cudaFuncSetAttribute(gemm_kernel, cudaFuncAttributeMaxDynamicSharedMemorySize, SMEM_DYN);
    dim3 grid(GRID_M, GRID_N);   // x = mtile fast => co-resident CTAs share W tiles in L2
    gemm_kernel<<<grid, THREADS, SMEM_DYN>>>(out);
}

// round 11
// speedup vs baseline: 1.0017x; 1.0017x over previous
#include <cuda_runtime.h>
#include <cuda_fp16.h>
#include <cstdint>
#include <cstddef>

// ---------------- problem dims ----------------
#define MM 16384    // B*S
#define NN 4096     // DOUT
#define KK 4096     // DIN

#define BM 128
#define BN 128
#define BK 64
#define NKT (KK / BK)      // 64
#define GRID_M (MM / BM)   // 128
#define GRID_N (NN / BN)   // 32
#define NCTAS (GRID_M * GRID_N)
#define THREADS 256
#define STAGES 3

// supertile swizzle: groups of SW_M mtiles x all ntiles stay co-resident
#define SW_M 8
#define GROUP (SW_M * GRID_N)   // 256 CTAs per group (16 exact groups)

#define STAGE_BYTES (BM * BK * 2 + BN * BK * 2)   // 16KB A + 16KB B = 32KB
#define SMEM_DYN (STAGES * STAGE_BYTES + 256)     // ~96.25KB -> 2 CTAs/SM

// ---------------- device scratch ----------------
__device__ __half g_A[(size_t)MM * KK];   // x in fp16 (128 MB)
__device__ __half g_W[(size_t)NN * KK];   // quantized weights: exact small integers in fp16
__device__ float  g_qb[NN];               // quantized bias * (1/255)

// ---------------- helpers ----------------
__device__ __forceinline__ uint32_t smem_u32(const void* p) {
    uint32_t a;
    asm("{ .reg .u64 t; cvta.to.shared.u64 t, %1; cvt.u32.u64 %0, t; }" : "=r"(a) : "l"(p));
    return a;
}
__device__ __forceinline__ void cp_async_cg(uint32_t s, const void* g) {
    asm volatile("cp.async.cg.shared.global [%0], [%1], 16;" :: "r"(s), "l"(g));
}
__device__ __forceinline__ void cp_commit() { asm volatile("cp.async.commit_group;" ::: "memory"); }

__device__ __forceinline__ void ldmatrix_x4(uint32_t& r0, uint32_t& r1, uint32_t& r2, uint32_t& r3,
                                            uint32_t addr) {
    asm volatile("ldmatrix.sync.aligned.m8n8.x4.shared.b16 {%0,%1,%2,%3}, [%4];"
                 : "=r"(r0), "=r"(r1), "=r"(r2), "=r"(r3) : "r"(addr));
}
__device__ __forceinline__ void mma16816(float& c0, float& c1, float& c2, float& c3,
                                         uint32_t a0, uint32_t a1, uint32_t a2, uint32_t a3,
                                         uint32_t b0, uint32_t b1) {
    asm volatile("mma.sync.aligned.m16n8k16.row.col.f32.f16.f16.f32 "
                 "{%0,%1,%2,%3}, {%4,%5,%6,%7}, {%8,%9}, {%0,%1,%2,%3};"
                 : "+f"(c0), "+f"(c1), "+f"(c2), "+f"(c3)
                 : "r"(a0), "r"(a1), "r"(a2), "r"(a3), "r"(b0), "r"(b1));
}

// ---------------- fused prepass ----------------
__device__ __forceinline__ float qstep(float t) {
    t = fminf(fmaxf(t, -1.0f), 1.0f);
    return copysignf(rintf(fabsf(t) * 255.0f), t);   // exact integer in [-255, 255]
}

#define XCHUNKS (MM * (size_t)KK / 4 / 256)   // 65536 blocks of 256 thr, 1 float4 each
#define WCHUNKS (NN * (size_t)KK / 4 / 256)   // 16384 blocks
#define BCHUNKS (NN / 256)                    // 16 blocks

__global__ void prepass_kernel(const float4* __restrict__ x,
                               const float4* __restrict__ w,
                               const float*  __restrict__ b) {
    size_t blk = blockIdx.x;
    if (blk < XCHUNKS) {
        size_t i = blk * 256 + threadIdx.x;
        float4 v = x[i];
        __half2* a2 = reinterpret_cast<__half2*>(g_A);
        a2[2 * i]     = __floats2half2_rn(v.x, v.y);
        a2[2 * i + 1] = __floats2half2_rn(v.z, v.w);
    } else if (blk < XCHUNKS + WCHUNKS) {
        size_t i = (blk - XCHUNKS) * 256 + threadIdx.x;
        float4 v = w[i];
        __half2* w2 = reinterpret_cast<__half2*>(g_W);
        w2[2 * i]     = __floats2half2_rn(qstep(v.x), qstep(v.y));  // exact
        w2[2 * i + 1] = __floats2half2_rn(qstep(v.z), qstep(v.w));
    } else {
        size_t i = (blk - XCHUNKS - WCHUNKS) * 256 + threadIdx.x;
        g_qb[i] = qstep(b[i]) * (1.0f / 255.0f);
    }
}

// ---------------- GEMM: cp.async triple-buffer + ldmatrix + mma.sync ----------------
// SMEM tile layout (per stage): rows of 64 halves = 8 chunks of 16B.
// chunk swizzle: physical chunk = c ^ (row & 7)  -> conflict-free cp.async stores
// and ldmatrix reads.
__global__ void __launch_bounds__(THREADS, 2)
gemm_kernel(float* __restrict__ out) {
    extern __shared__ char dynsmem[];
    uint32_t sb = (smem_u32(dynsmem) + 255u) & ~255u;

    const int tid  = threadIdx.x;
    const int lane = tid & 31;
    const int wid  = tid >> 5;
    const int wm   = wid & 3;    // 4 warps along M: 32 rows each
    const int wn   = wid >> 2;   // 2 warps along N: 64 cols each

    // supertile swizzle: bid -> (mtile, ntile); one group = 8 mtiles x 32 ntiles,
    // so a ~296-CTA wave keeps its A slice (8 MB) + all W hot in L2.
    const int bid   = blockIdx.x;
    const int grp   = bid / GROUP;
    const int rem   = bid % GROUP;
    const int mtile = grp * SW_M + (rem % SW_M);
    const int ntile = rem / SW_M;

    const __half* Ab = g_A + (size_t)mtile * BM * KK;
    const __half* Wb = g_W + (size_t)ntile * BN * KK;

    // per-stage loader: A tile 128x64, B tile 128x64; 1024 chunks each, 4+4 per thread
    auto load_tile = [&](int kt, int s) {
        uint32_t abase = sb + s * STAGE_BYTES;
        uint32_t bbase = abase + BM * BK * 2;
        const __half* Ak = Ab + (size_t)kt * BK;
        const __half* Wk = Wb + (size_t)kt * BK;
        #pragma unroll
        for (int j = 0; j < 4; j++) {
            int id = j * THREADS + tid;
            int row = id >> 3, c = id & 7;
            uint32_t dst = (uint32_t)(row * 8 + (c ^ (row & 7))) * 16;
            cp_async_cg(abase + dst, Ak + (size_t)row * KK + c * 8);
        }
        #pragma unroll
        for (int j = 0; j < 4; j++) {
            int id = j * THREADS + tid;
            int row = id >> 3, c = id & 7;
            uint32_t dst = (uint32_t)(row * 8 + (c ^ (row & 7))) * 16;
            cp_async_cg(bbase + dst, Wk + (size_t)row * KK + c * 8);
        }
        cp_commit();
    };

    float acc[2][8][4];
    #pragma unroll
    for (int i = 0; i < 2; i++)
        #pragma unroll
        for (int j = 0; j < 8; j++)
            #pragma unroll
            for (int k = 0; k < 4; k++) acc[i][j][k] = 0.0f;

    const int lrow = lane & 15;   // ldmatrix row within 16
    const int lsel = lane >> 4;   // ldmatrix chunk select (0/1)

    load_tile(0, 0);
    load_tile(1, 1);
    load_tile(2, 2);

    int s = 0;
    for (int kt = 0; kt < NKT; kt++) {
        if (kt + 3 < NKT)      asm volatile("cp.async.wait_group 2;" ::: "memory");
        else if (kt + 2 < NKT) asm volatile("cp.async.wait_group 1;" ::: "memory");
        else                   asm volatile("cp.async.wait_group 0;" ::: "memory");
        __syncthreads();

        uint32_t abase = sb + s * STAGE_BYTES;
        uint32_t bbase = abase + BM * BK * 2;

        #pragma unroll
        for (int ks = 0; ks < 4; ks++) {          // BK=64 -> 4 k16 steps
            // A fragments: 2 m16 tiles
            uint32_t a[2][4];
            #pragma unroll
            for (int mt = 0; mt < 2; mt++) {
                int r = wm * 32 + mt * 16 + lrow;
                int c = ks * 2 + lsel;
                uint32_t addr = abase + (uint32_t)(r * 8 + (c ^ (r & 7))) * 16;
                ldmatrix_x4(a[mt][0], a[mt][1], a[mt][2], a[mt][3], addr);
            }
            // B fragments: 4 n16 tiles (each = two n8 frags)
            uint32_t b[4][4];
            #pragma unroll
            for (int nt = 0; nt < 4; nt++) {
                int r = wn * 64 + nt * 16 + lrow;
                int c = ks * 2 + lsel;
                uint32_t addr = bbase + (uint32_t)(r * 8 + (c ^ (r & 7))) * 16;
                ldmatrix_x4(b[nt][0], b[nt][1], b[nt][2], b[nt][3], addr);
            }
            #pragma unroll
            for (int mt = 0; mt < 2; mt++)
                #pragma unroll
                for (int nt = 0; nt < 4; nt++) {
                    // n8 frag 0: regs {0,2}; n8 frag 1: regs {1,3}
                    mma16816(acc[mt][nt*2][0], acc[mt][nt*2][1], acc[mt][nt*2][2], acc[mt][nt*2][3],
                             a[mt][0], a[mt][1], a[mt][2], a[mt][3], b[nt][0], b[nt][2]);
                    mma16816(acc[mt][nt*2+1][0], acc[mt][nt*2+1][1], acc[mt][nt*2+1][2], acc[mt][nt*2+1][3],
                             a[mt][0], a[mt][1], a[mt][2], a[mt][3], b[nt][1], b[nt][3]);
                }
        }
        __syncthreads();
        if (kt + 3 < NKT) load_tile(kt + 3, s);
        s = (s == STAGES - 1) ? 0 : s + 1;
    }

    // ---------------- epilogue: out = acc * (1/255) + qb (streaming stores) ----------------
    const int tm = lane >> 2;          // 0..7
    const int tn = (lane & 3) * 2;     // 0,2,4,6
    const float inv = 1.0f / 255.0f;   // weights stored as integer codes k = qw*255
    const float* qbb = g_qb + ntile * BN + wn * 64;

    float2 bias[8];
    #pragma unroll
    for (int nn = 0; nn < 8; nn++) {
        int col = (nn >> 1) * 16 + (nn & 1) * 8 + tn;
        bias[nn] = *(const float2*)(qbb + col);
    }

    #pragma unroll
    for (int mt = 0; mt < 2; mt++) {
        #pragma unroll
        for (int h = 0; h < 2; h++) {           // c0c1 (row+0) / c2c3 (row+8)
            int row = mtile * BM + wm * 32 + mt * 16 + tm + h * 8;
            float* orow = out + (size_t)row * NN + ntile * BN + wn * 64;
            #pragma unroll
            for (int nn = 0; nn < 8; nn++) {
                int col = (nn >> 1) * 16 + (nn & 1) * 8 + tn;
                float2 v;
                v.x = fmaf(acc[mt][nn][h * 2 + 0], inv, bias[nn].x);
                v.y = fmaf(acc[mt][nn][h * 2 + 1], inv, bias[nn].y);
                __stcs((float2*)(orow + col), v);   // evict-first: don't pollute L2
            }
        }
    }
}

// ---------------- launch ----------------
extern "C" void kernel_launch(void* const* d_in, const int* in_sizes, int n_in,
                              void* d_out, int out_size) {
    const float* x = (const float*)d_in[0];
    const float* w = (const float*)d_in[1];
    const float* b = (const float*)d_in[2];
    float* out = (float*)d_out;

    prepass_kernel<<<(unsigned)(XCHUNKS + WCHUNKS + BCHUNKS), 256>>>(
        (const float4*)x, (const float4*)w, b);

    cudaFuncSetAttribute(gemm_kernel, cudaFuncAttributeMaxDynamicSharedMemorySize, SMEM_DYN);
    gemm_kernel<<<NCTAS, THREADS, SMEM_DYN>>>(out);
}